// round 1
// baseline (speedup 1.0000x reference)
#include <cuda_runtime.h>
#include <cstdint>
#include <math.h>

#define N_TOK 8192
#define DIM   2048
#define FF    5632
#define NE    8

// ---------------- scratch (device globals; no allocations allowed) ----------
__device__ int   g_cnt[NE];
__device__ float g_psum[NE];
__device__ int   g_off[NE];
__device__ int   g_cursor[NE];
__device__ int   g_top_id[N_TOK * 2];
__device__ float g_top_w[N_TOK * 2];
__device__ int   g_row_tok[N_TOK * 2];
__device__ float g_row_w[N_TOK * 2];
// H buffer: 16384 rows x 5632 fp32 = 369 MB
__device__ float g_H[(size_t)N_TOK * 2 * FF];

// ---------------- small init ------------------------------------------------
__global__ void zero_small_kernel() {
    int i = threadIdx.x;
    if (i < NE) { g_cnt[i] = 0; g_psum[i] = 0.f; }
}

// ---------------- router: logits -> softmax -> top2 + stats ----------------
__global__ void router_kernel(const float* __restrict__ x,
                              const float* __restrict__ rw) {
    int warp = threadIdx.x >> 5;
    int lane = threadIdx.x & 31;
    int t = blockIdx.x * 8 + warp;
    if (t >= N_TOK) return;

    const float* xr = x + (size_t)t * DIM;
    float acc[NE];
#pragma unroll
    for (int e = 0; e < NE; e++) acc[e] = 0.f;

    for (int d = lane; d < DIM; d += 32) {
        float xv = xr[d];
#pragma unroll
        for (int e = 0; e < NE; e++) acc[e] += xv * rw[e * DIM + d];
    }
#pragma unroll
    for (int off = 16; off > 0; off >>= 1) {
#pragma unroll
        for (int e = 0; e < NE; e++)
            acc[e] += __shfl_xor_sync(0xffffffffu, acc[e], off);
    }
    // softmax (all lanes redundantly, lane0 commits)
    float mx = acc[0];
#pragma unroll
    for (int e = 1; e < NE; e++) mx = fmaxf(mx, acc[e]);
    float p[NE], s = 0.f;
#pragma unroll
    for (int e = 0; e < NE; e++) { p[e] = expf(acc[e] - mx); s += p[e]; }
    float inv = 1.f / s;
#pragma unroll
    for (int e = 0; e < NE; e++) p[e] *= inv;

    // top-2 (ties -> lower index first, matching lax.top_k)
    float m1 = -1.f, m2 = -1.f; int i1 = 0, i2 = 0;
#pragma unroll
    for (int e = 0; e < NE; e++) {
        if (p[e] > m1) { m2 = m1; i2 = i1; m1 = p[e]; i1 = e; }
        else if (p[e] > m2) { m2 = p[e]; i2 = e; }
    }

    if (lane == 0) {
        atomicAdd(&g_cnt[i1], 1);
        atomicAdd(&g_cnt[i2], 1);
#pragma unroll
        for (int e = 0; e < NE; e++) atomicAdd(&g_psum[e], p[e]);
        float sw = 1.f / (m1 + m2);
        g_top_id[2 * t + 0] = i1;  g_top_w[2 * t + 0] = m1 * sw;
        g_top_id[2 * t + 1] = i2;  g_top_w[2 * t + 1] = m2 * sw;
    }
}

// ---------------- finalize: offsets + aux loss ------------------------------
__global__ void finalize_kernel(float* __restrict__ out, long long out_size) {
    if (threadIdx.x != 0 || blockIdx.x != 0) return;
    int o = 0;
    for (int e = 0; e < NE; e++) {
        g_off[e] = o; g_cursor[e] = o; o += g_cnt[e];
    }
    float aux = 0.f;
    for (int e = 0; e < NE; e++) aux += g_psum[e] * (float)g_cnt[e];
    aux *= (float)NE / ((float)N_TOK * (float)N_TOK);
    if (out_size > (long long)N_TOK * DIM)
        out[(size_t)N_TOK * DIM] = aux;
}

// ---------------- scatter: build packed per-expert row lists ----------------
__global__ void scatter_kernel() {
    int t = blockIdx.x * blockDim.x + threadIdx.x;
    if (t >= N_TOK) return;
#pragma unroll
    for (int s = 0; s < 2; s++) {
        int e = g_top_id[2 * t + s];
        int pos = atomicAdd(&g_cursor[e], 1);
        g_row_tok[pos] = t;
        g_row_w[pos] = g_top_w[2 * t + s];
    }
}

// ---------------- grouped GEMM1: H = silu(X Gw^T) * (X Uw^T) -----------------
// tile 64x64, BK=16, 256 thr, 4x4 microtile, gate+up share A tile
__global__ __launch_bounds__(256)
void gemm1_kernel(const float* __restrict__ x,
                  const float* __restrict__ gw,
                  const float* __restrict__ uw) {
    int e   = blockIdx.z;
    int cnt = g_cnt[e];
    int m0  = blockIdx.y * 64;
    if (m0 >= cnt) return;
    int n0  = blockIdx.x * 64;
    int off = g_off[e];

    __shared__ float As[16][68];
    __shared__ float Bg[16][68];
    __shared__ float Bu[16][68];
    __shared__ int   s_tok[64];

    int tid = threadIdx.x;
    if (tid < 64) {
        int r = m0 + tid;
        s_tok[tid] = (r < cnt) ? g_row_tok[off + r] : 0;
    }
    __syncthreads();

    int lrow = tid >> 2, lkq = tid & 3;
    const float* abase = x  + (size_t)s_tok[lrow] * DIM + lkq * 4;
    const float* gbase = gw + ((size_t)e * FF + (n0 + lrow)) * DIM + lkq * 4;
    const float* ubase = uw + ((size_t)e * FF + (n0 + lrow)) * DIM + lkq * 4;

    int tx = tid & 15, ty = tid >> 4;
    float ag[4][4], au[4][4];
#pragma unroll
    for (int i = 0; i < 4; i++)
#pragma unroll
        for (int j = 0; j < 4; j++) { ag[i][j] = 0.f; au[i][j] = 0.f; }

    const int KT = DIM / 16;
    float4 va = *(const float4*)(abase);
    float4 vg = *(const float4*)(gbase);
    float4 vu = *(const float4*)(ubase);

    for (int kt = 0; kt < KT; kt++) {
        int kb = lkq * 4;
        As[kb+0][lrow]=va.x; As[kb+1][lrow]=va.y; As[kb+2][lrow]=va.z; As[kb+3][lrow]=va.w;
        Bg[kb+0][lrow]=vg.x; Bg[kb+1][lrow]=vg.y; Bg[kb+2][lrow]=vg.z; Bg[kb+3][lrow]=vg.w;
        Bu[kb+0][lrow]=vu.x; Bu[kb+1][lrow]=vu.y; Bu[kb+2][lrow]=vu.z; Bu[kb+3][lrow]=vu.w;
        __syncthreads();
        if (kt + 1 < KT) {
            va = *(const float4*)(abase + (size_t)(kt + 1) * 16);
            vg = *(const float4*)(gbase + (size_t)(kt + 1) * 16);
            vu = *(const float4*)(ubase + (size_t)(kt + 1) * 16);
        }
#pragma unroll
        for (int k = 0; k < 16; k++) {
            float4 a4 = *(const float4*)&As[k][ty * 4];
            float4 g4 = *(const float4*)&Bg[k][tx * 4];
            float4 u4 = *(const float4*)&Bu[k][tx * 4];
            float av[4] = {a4.x, a4.y, a4.z, a4.w};
            float gv[4] = {g4.x, g4.y, g4.z, g4.w};
            float uv[4] = {u4.x, u4.y, u4.z, u4.w};
#pragma unroll
            for (int i = 0; i < 4; i++)
#pragma unroll
                for (int j = 0; j < 4; j++) {
                    ag[i][j] += av[i] * gv[j];
                    au[i][j] += av[i] * uv[j];
                }
        }
        __syncthreads();
    }

    // epilogue: h = silu(g) * u -> H
#pragma unroll
    for (int i = 0; i < 4; i++) {
        int r = m0 + ty * 4 + i;
        if (r < cnt) {
            float4 h;
            float g0 = ag[i][0], g1 = ag[i][1], g2 = ag[i][2], g3 = ag[i][3];
            h.x = g0 / (1.f + expf(-g0)) * au[i][0];
            h.y = g1 / (1.f + expf(-g1)) * au[i][1];
            h.z = g2 / (1.f + expf(-g2)) * au[i][2];
            h.w = g3 / (1.f + expf(-g3)) * au[i][3];
            *(float4*)&g_H[(size_t)(off + r) * FF + n0 + tx * 4] = h;
        }
    }
}

// ---------------- grouped GEMM2: out += w * (H Dw^T) -------------------------
__global__ __launch_bounds__(256)
void gemm2_kernel(const float* __restrict__ dw, float* __restrict__ out) {
    int e   = blockIdx.z;
    int cnt = g_cnt[e];
    int m0  = blockIdx.y * 64;
    if (m0 >= cnt) return;
    int n0  = blockIdx.x * 64;
    int off = g_off[e];

    __shared__ float As[16][68];
    __shared__ float Bs[16][68];
    __shared__ int   s_tok[64];
    __shared__ float s_w[64];

    int tid = threadIdx.x;
    if (tid < 64) {
        int r = m0 + tid;
        bool v = (r < cnt);
        s_tok[tid] = v ? g_row_tok[off + r] : 0;
        s_w[tid]   = v ? g_row_w[off + r] : 0.f;
    }

    int lrow = tid >> 2, lkq = tid & 3;
    int rr = m0 + lrow; if (rr >= cnt) rr = 0;   // clamp: stay in-bounds of g_H
    const float* abase = g_H + (size_t)(off + rr) * FF + lkq * 4;
    const float* bbase = dw  + ((size_t)e * DIM + (n0 + lrow)) * FF + lkq * 4;

    int tx = tid & 15, ty = tid >> 4;
    float acc[4][4];
#pragma unroll
    for (int i = 0; i < 4; i++)
#pragma unroll
        for (int j = 0; j < 4; j++) acc[i][j] = 0.f;

    const int KT = FF / 16;
    float4 va = *(const float4*)(abase);
    float4 vb = *(const float4*)(bbase);

    for (int kt = 0; kt < KT; kt++) {
        int kb = lkq * 4;
        As[kb+0][lrow]=va.x; As[kb+1][lrow]=va.y; As[kb+2][lrow]=va.z; As[kb+3][lrow]=va.w;
        Bs[kb+0][lrow]=vb.x; Bs[kb+1][lrow]=vb.y; Bs[kb+2][lrow]=vb.z; Bs[kb+3][lrow]=vb.w;
        __syncthreads();
        if (kt + 1 < KT) {
            va = *(const float4*)(abase + (size_t)(kt + 1) * 16);
            vb = *(const float4*)(bbase + (size_t)(kt + 1) * 16);
        }
#pragma unroll
        for (int k = 0; k < 16; k++) {
            float4 a4 = *(const float4*)&As[k][ty * 4];
            float4 b4 = *(const float4*)&Bs[k][tx * 4];
            float av[4] = {a4.x, a4.y, a4.z, a4.w};
            float bv[4] = {b4.x, b4.y, b4.z, b4.w};
#pragma unroll
            for (int i = 0; i < 4; i++)
#pragma unroll
                for (int j = 0; j < 4; j++)
                    acc[i][j] += av[i] * bv[j];
        }
        __syncthreads();
    }

    // epilogue: weighted scatter-add into out (exactly 2 adds/element -> exact)
#pragma unroll
    for (int i = 0; i < 4; i++) {
        int r = m0 + ty * 4 + i;
        if (r < cnt) {
            int tok = s_tok[ty * 4 + i];
            float w = s_w[ty * 4 + i];
            float* orow = out + (size_t)tok * DIM + n0 + tx * 4;
            atomicAdd(orow + 0, w * acc[i][0]);
            atomicAdd(orow + 1, w * acc[i][1]);
            atomicAdd(orow + 2, w * acc[i][2]);
            atomicAdd(orow + 3, w * acc[i][3]);
        }
    }
}

// ---------------- launcher ---------------------------------------------------
extern "C" void kernel_launch(void* const* d_in, const int* in_sizes, int n_in,
                              void* d_out, int out_size) {
    const float* x  = (const float*)d_in[0];
    const float* rw = (const float*)d_in[1];
    const float* gw = (const float*)d_in[2];
    const float* uw = (const float*)d_in[3];
    const float* dw = (const float*)d_in[4];
    float* out = (float*)d_out;

    cudaMemsetAsync(out, 0, (size_t)N_TOK * DIM * sizeof(float));
    zero_small_kernel<<<1, 32>>>();
    router_kernel<<<N_TOK / 8, 256>>>(x, rw);
    finalize_kernel<<<1, 1>>>(out, (long long)out_size);
    scatter_kernel<<<N_TOK / 256, 256>>>();
    gemm1_kernel<<<dim3(FF / 64, N_TOK / 64, NE), 256>>>(x, gw, uw);
    gemm2_kernel<<<dim3(DIM / 64, N_TOK / 64, NE), 256>>>(dw, out);
}

// round 3
// speedup vs baseline: 2.6837x; 2.6837x over previous
#include <cuda_runtime.h>
#include <cuda_bf16.h>
#include <cstdint>
#include <math.h>

#define N_TOK 8192
#define DIM   2048
#define FF    5632
#define NE    8

// ===================== helpers =============================================
__device__ __forceinline__ uint32_t smem_to_u32(const void* p) {
    uint32_t a;
    asm("{ .reg .u64 t; cvta.to.shared.u64 t, %1; cvt.u32.u64 %0, t; }"
        : "=r"(a) : "l"(p));
    return a;
}

#define LDSM_X4(r0, r1, r2, r3, addr) \
    asm volatile("ldmatrix.sync.aligned.m8n8.x4.shared.b16 {%0,%1,%2,%3}, [%4];" \
                 : "=r"(r0), "=r"(r1), "=r"(r2), "=r"(r3) : "r"(addr))

#define MMA16816(c, a, b0, b1) \
    asm volatile("mma.sync.aligned.m16n8k16.row.col.f32.bf16.bf16.f32 " \
                 "{%0,%1,%2,%3},{%4,%5,%6,%7},{%8,%9},{%0,%1,%2,%3};" \
                 : "+f"((c)[0]), "+f"((c)[1]), "+f"((c)[2]), "+f"((c)[3]) \
                 : "r"((a)[0]), "r"((a)[1]), "r"((a)[2]), "r"((a)[3]), \
                   "r"(b0), "r"(b1))

// fp32 -> (hi,lo) bf16 split, 2 values packed per uint32
__device__ __forceinline__ void split2(float a, float b, uint32_t& hi, uint32_t& lo) {
    __nv_bfloat16 ha = __float2bfloat16_rn(a);
    __nv_bfloat16 hb = __float2bfloat16_rn(b);
    float ra = a - __bfloat162float(ha);
    float rb = b - __bfloat162float(hb);
    __nv_bfloat162 h; h.x = ha; h.y = hb;
    __nv_bfloat162 l; l.x = __float2bfloat16_rn(ra); l.y = __float2bfloat16_rn(rb);
    hi = *reinterpret_cast<uint32_t*>(&h);
    lo = *reinterpret_cast<uint32_t*>(&l);
}

__device__ __forceinline__ void store_split8(char* dhi, char* dlo, float4 a, float4 b) {
    uint32_t h0, l0, h1, l1, h2, l2, h3, l3;
    split2(a.x, a.y, h0, l0);
    split2(a.z, a.w, h1, l1);
    split2(b.x, b.y, h2, l2);
    split2(b.z, b.w, h3, l3);
    *(uint4*)dhi = make_uint4(h0, h1, h2, h3);
    *(uint4*)dlo = make_uint4(l0, l1, l2, l3);
}

// byte offset within a [rows][32 bf16] tile, 64B rows, xor swizzle for ldmatrix
__device__ __forceinline__ uint32_t tile_off(int row, int chunk) {
    return (uint32_t)(row * 64 + ((chunk ^ ((row >> 1) & 3)) << 4));
}

// ===================== scratch =============================================
__device__ int   g_cnt[NE];
__device__ float g_psum[NE];
__device__ int   g_off[NE];
__device__ int   g_cursor[NE];
__device__ int   g_top_id[N_TOK * 2];
__device__ float g_top_w[N_TOK * 2];
__device__ int   g_row_tok[N_TOK * 2];
__device__ float g_row_w[N_TOK * 2];
__device__ __align__(16) __nv_bfloat16 g_Hhi[(size_t)N_TOK * 2 * FF];
__device__ __align__(16) __nv_bfloat16 g_Hlo[(size_t)N_TOK * 2 * FF];

// ===================== router pipeline ======================================
__global__ void zero_small_kernel() {
    int i = threadIdx.x;
    if (i < NE) { g_cnt[i] = 0; g_psum[i] = 0.f; }
}

__global__ void router_kernel(const float* __restrict__ x,
                              const float* __restrict__ rw) {
    int warp = threadIdx.x >> 5;
    int lane = threadIdx.x & 31;
    int t = blockIdx.x * 8 + warp;
    if (t >= N_TOK) return;
    const float* xr = x + (size_t)t * DIM;
    float acc[NE];
#pragma unroll
    for (int e = 0; e < NE; e++) acc[e] = 0.f;
    for (int d = lane; d < DIM; d += 32) {
        float xv = xr[d];
#pragma unroll
        for (int e = 0; e < NE; e++) acc[e] += xv * rw[e * DIM + d];
    }
#pragma unroll
    for (int off = 16; off > 0; off >>= 1) {
#pragma unroll
        for (int e = 0; e < NE; e++)
            acc[e] += __shfl_xor_sync(0xffffffffu, acc[e], off);
    }
    float mx = acc[0];
#pragma unroll
    for (int e = 1; e < NE; e++) mx = fmaxf(mx, acc[e]);
    float p[NE], s = 0.f;
#pragma unroll
    for (int e = 0; e < NE; e++) { p[e] = expf(acc[e] - mx); s += p[e]; }
    float inv = 1.f / s;
#pragma unroll
    for (int e = 0; e < NE; e++) p[e] *= inv;
    float m1 = -1.f, m2 = -1.f; int i1 = 0, i2 = 0;
#pragma unroll
    for (int e = 0; e < NE; e++) {
        if (p[e] > m1) { m2 = m1; i2 = i1; m1 = p[e]; i1 = e; }
        else if (p[e] > m2) { m2 = p[e]; i2 = e; }
    }
    if (lane == 0) {
        atomicAdd(&g_cnt[i1], 1);
        atomicAdd(&g_cnt[i2], 1);
#pragma unroll
        for (int e = 0; e < NE; e++) atomicAdd(&g_psum[e], p[e]);
        float sw = 1.f / (m1 + m2);
        g_top_id[2 * t + 0] = i1;  g_top_w[2 * t + 0] = m1 * sw;
        g_top_id[2 * t + 1] = i2;  g_top_w[2 * t + 1] = m2 * sw;
    }
}

__global__ void finalize_kernel(float* __restrict__ out, long long out_size) {
    if (threadIdx.x != 0 || blockIdx.x != 0) return;
    int o = 0;
    for (int e = 0; e < NE; e++) { g_off[e] = o; g_cursor[e] = o; o += g_cnt[e]; }
    float aux = 0.f;
    for (int e = 0; e < NE; e++) aux += g_psum[e] * (float)g_cnt[e];
    aux *= (float)NE / ((float)N_TOK * (float)N_TOK);
    if (out_size > (long long)N_TOK * DIM)
        out[(size_t)N_TOK * DIM] = aux;
}

__global__ void scatter_kernel() {
    int t = blockIdx.x * blockDim.x + threadIdx.x;
    if (t >= N_TOK) return;
#pragma unroll
    for (int s = 0; s < 2; s++) {
        int e = g_top_id[2 * t + s];
        int pos = atomicAdd(&g_cursor[e], 1);
        g_row_tok[pos] = t;
        g_row_w[pos] = g_top_w[2 * t + s];
    }
}

// ===================== GEMM1: H = silu(X Gw^T) * (X Uw^T) ===================
// mma.sync bf16 3-term split. CTA tile 128x64 (per matrix), BK=32, 256 thr.
#define S1_AH 0
#define S1_AL 8192
#define S1_GH 16384
#define S1_GL 20480
#define S1_UH 24576
#define S1_UL 28672
#define STAGE1 32768
#define G1_SMEM (2 * STAGE1)

__global__ __launch_bounds__(256)
void gemm1_mma(const float* __restrict__ x,
               const float* __restrict__ gw,
               const float* __restrict__ uw) {
    int e   = blockIdx.z;
    int cnt = g_cnt[e];
    int m0  = blockIdx.y * 128;
    if (m0 >= cnt) return;
    int n0  = blockIdx.x * 64;
    int off = g_off[e];

    extern __shared__ char sm[];
    __shared__ int s_tok[128];
    int tid = threadIdx.x;
    if (tid < 128) {
        int rr = m0 + tid;
        s_tok[tid] = (rr < cnt) ? g_row_tok[off + rr] : g_row_tok[off];
    }
    __syncthreads();
    uint32_t sbu = smem_to_u32(sm);

    // ---- fill mapping
    int arow = tid >> 1;
    int acb  = (tid & 1) * 2;                       // chunk pair base (0 or 2)
    const float* apA = x + (size_t)s_tok[arow] * DIM + acb * 8;
    int brow = tid >> 2;
    int bch  = tid & 3;
    const float* apG = gw + ((size_t)e * FF + n0 + brow) * DIM + bch * 8;
    const float* apU = uw + ((size_t)e * FF + n0 + brow) * DIM + bch * 8;

    // ---- frag mapping
    int lane = tid & 31, warp = tid >> 5;
    int wm = warp & 3, wn = warp >> 2;              // 4 x 2 warp grid, 32x32 tiles
    int laneA_row = lane & 15;
    int laneA_c   = lane >> 4;
    int laneB_row = (lane & 7) | ((lane >> 1) & 8);
    int laneB_c   = (lane >> 3) & 1;

    float gacc[2][4][4], uacc[2][4][4];
#pragma unroll
    for (int i = 0; i < 2; i++)
#pragma unroll
        for (int j = 0; j < 4; j++)
#pragma unroll
            for (int k = 0; k < 4; k++) { gacc[i][j][k] = 0.f; uacc[i][j][k] = 0.f; }

    float4 av[4], bgv[2], buv[2];
    const int NS = DIM / 32;  // 64

    // prologue: stage 0
    av[0] = *(const float4*)(apA + 0);
    av[1] = *(const float4*)(apA + 4);
    av[2] = *(const float4*)(apA + 8);
    av[3] = *(const float4*)(apA + 12);
    bgv[0] = *(const float4*)(apG + 0);
    bgv[1] = *(const float4*)(apG + 4);
    buv[0] = *(const float4*)(apU + 0);
    buv[1] = *(const float4*)(apU + 4);
    {
        char* st = sm;
        store_split8(st + S1_AH + tile_off(arow, acb),     st + S1_AL + tile_off(arow, acb),     av[0], av[1]);
        store_split8(st + S1_AH + tile_off(arow, acb + 1), st + S1_AL + tile_off(arow, acb + 1), av[2], av[3]);
        store_split8(st + S1_GH + tile_off(brow, bch),     st + S1_GL + tile_off(brow, bch),     bgv[0], bgv[1]);
        store_split8(st + S1_UH + tile_off(brow, bch),     st + S1_UL + tile_off(brow, bch),     buv[0], buv[1]);
    }
    __syncthreads();

#pragma unroll 1
    for (int s = 0; s < NS; s++) {
        if (s + 1 < NS) {
            const float* pa = apA + (s + 1) * 32;
            av[0] = *(const float4*)(pa + 0);
            av[1] = *(const float4*)(pa + 4);
            av[2] = *(const float4*)(pa + 8);
            av[3] = *(const float4*)(pa + 12);
            const float* pg = apG + (s + 1) * 32;
            bgv[0] = *(const float4*)(pg + 0);
            bgv[1] = *(const float4*)(pg + 4);
            const float* pu = apU + (s + 1) * 32;
            buv[0] = *(const float4*)(pu + 0);
            buv[1] = *(const float4*)(pu + 4);
        }
        uint32_t sb = sbu + (uint32_t)(s & 1) * STAGE1;
#pragma unroll
        for (int kk = 0; kk < 2; kk++) {
            int c0 = kk * 2;
            uint32_t ah[2][4], al[2][4];
#pragma unroll
            for (int mt = 0; mt < 2; mt++) {
                int row = wm * 32 + mt * 16 + laneA_row;
                int ch  = c0 + laneA_c;
                uint32_t ad = sb + S1_AH + tile_off(row, ch);
                LDSM_X4(ah[mt][0], ah[mt][1], ah[mt][2], ah[mt][3], ad);
                LDSM_X4(al[mt][0], al[mt][1], al[mt][2], al[mt][3], ad + (S1_AL - S1_AH));
            }
            {   // gate
                uint32_t bh[2][4], bl[2][4];
#pragma unroll
                for (int g2 = 0; g2 < 2; g2++) {
                    int row = wn * 32 + g2 * 16 + laneB_row;
                    int ch  = c0 + laneB_c;
                    uint32_t bd = sb + S1_GH + tile_off(row, ch);
                    LDSM_X4(bh[g2][0], bh[g2][1], bh[g2][2], bh[g2][3], bd);
                    LDSM_X4(bl[g2][0], bl[g2][1], bl[g2][2], bl[g2][3], bd + (S1_GL - S1_GH));
                }
#pragma unroll
                for (int mt = 0; mt < 2; mt++)
#pragma unroll
                    for (int nt = 0; nt < 4; nt++) {
                        int gi = nt >> 1, pi = (nt & 1) * 2;
                        MMA16816(gacc[mt][nt], ah[mt], bh[gi][pi], bh[gi][pi + 1]);
                        MMA16816(gacc[mt][nt], ah[mt], bl[gi][pi], bl[gi][pi + 1]);
                        MMA16816(gacc[mt][nt], al[mt], bh[gi][pi], bh[gi][pi + 1]);
                    }
            }
            {   // up
                uint32_t bh[2][4], bl[2][4];
#pragma unroll
                for (int g2 = 0; g2 < 2; g2++) {
                    int row = wn * 32 + g2 * 16 + laneB_row;
                    int ch  = c0 + laneB_c;
                    uint32_t bd = sb + S1_UH + tile_off(row, ch);
                    LDSM_X4(bh[g2][0], bh[g2][1], bh[g2][2], bh[g2][3], bd);
                    LDSM_X4(bl[g2][0], bl[g2][1], bl[g2][2], bl[g2][3], bd + (S1_UL - S1_UH));
                }
#pragma unroll
                for (int mt = 0; mt < 2; mt++)
#pragma unroll
                    for (int nt = 0; nt < 4; nt++) {
                        int gi = nt >> 1, pi = (nt & 1) * 2;
                        MMA16816(uacc[mt][nt], ah[mt], bh[gi][pi], bh[gi][pi + 1]);
                        MMA16816(uacc[mt][nt], ah[mt], bl[gi][pi], bl[gi][pi + 1]);
                        MMA16816(uacc[mt][nt], al[mt], bh[gi][pi], bh[gi][pi + 1]);
                    }
            }
        }
        __syncthreads();
        if (s + 1 < NS) {
            char* st = sm + ((s + 1) & 1) * STAGE1;
            store_split8(st + S1_AH + tile_off(arow, acb),     st + S1_AL + tile_off(arow, acb),     av[0], av[1]);
            store_split8(st + S1_AH + tile_off(arow, acb + 1), st + S1_AL + tile_off(arow, acb + 1), av[2], av[3]);
            store_split8(st + S1_GH + tile_off(brow, bch),     st + S1_GL + tile_off(brow, bch),     bgv[0], bgv[1]);
            store_split8(st + S1_UH + tile_off(brow, bch),     st + S1_UL + tile_off(brow, bch),     buv[0], buv[1]);
            __syncthreads();
        }
    }

    // epilogue: h = silu(g)*u -> split bf16 hi/lo -> g_H
#pragma unroll
    for (int mt = 0; mt < 2; mt++) {
#pragma unroll
        for (int half = 0; half < 2; half++) {
            int rr = m0 + wm * 32 + mt * 16 + (lane >> 2) + half * 8;
            if (rr < cnt) {
                size_t rb = (size_t)(off + rr) * FF + n0 + wn * 32 + (lane & 3) * 2;
#pragma unroll
                for (int nt = 0; nt < 4; nt++) {
                    float g0 = gacc[mt][nt][half * 2 + 0];
                    float g1 = gacc[mt][nt][half * 2 + 1];
                    float u0 = uacc[mt][nt][half * 2 + 0];
                    float u1 = uacc[mt][nt][half * 2 + 1];
                    float h0 = g0 / (1.f + __expf(-g0)) * u0;
                    float h1 = g1 / (1.f + __expf(-g1)) * u1;
                    uint32_t hh, hl;
                    split2(h0, h1, hh, hl);
                    *(uint32_t*)(g_Hhi + rb + nt * 8) = hh;
                    *(uint32_t*)(g_Hlo + rb + nt * 8) = hl;
                }
            }
        }
    }
}

// ===================== GEMM2: out += w * (H Dw^T) ===========================
#define S2_AH 0
#define S2_AL 8192
#define S2_BH 16384
#define S2_BL 20480
#define STAGE2 24576
#define G2_SMEM (2 * STAGE2)

__global__ __launch_bounds__(256)
void gemm2_mma(const float* __restrict__ dw, float* __restrict__ out) {
    int e   = blockIdx.z;
    int cnt = g_cnt[e];
    int m0  = blockIdx.y * 128;
    if (m0 >= cnt) return;
    int n0  = blockIdx.x * 64;
    int off = g_off[e];

    extern __shared__ char sm[];
    __shared__ int   s_tok[128];
    __shared__ float s_w[128];
    int tid = threadIdx.x;
    if (tid < 128) {
        int rr = m0 + tid;
        bool v = rr < cnt;
        s_tok[tid] = v ? g_row_tok[off + rr] : 0;
        s_w[tid]   = v ? g_row_w[off + rr] : 0.f;
    }
    __syncthreads();
    uint32_t sbu = smem_to_u32(sm);

    int arow = tid >> 1;
    int acb  = (tid & 1) * 2;
    int hr   = (m0 + arow < cnt) ? (off + m0 + arow) : off;
    const __nv_bfloat16* apHh = g_Hhi + (size_t)hr * FF + acb * 8;
    const __nv_bfloat16* apHl = g_Hlo + (size_t)hr * FF + acb * 8;
    int brow = tid >> 2;
    int bch  = tid & 3;
    const float* apB = dw + ((size_t)e * DIM + n0 + brow) * FF + bch * 8;

    int lane = tid & 31, warp = tid >> 5;
    int wm = warp & 3, wn = warp >> 2;
    int laneA_row = lane & 15;
    int laneA_c   = lane >> 4;
    int laneB_row = (lane & 7) | ((lane >> 1) & 8);
    int laneB_c   = (lane >> 3) & 1;

    float acc[2][4][4];
#pragma unroll
    for (int i = 0; i < 2; i++)
#pragma unroll
        for (int j = 0; j < 4; j++)
#pragma unroll
            for (int k = 0; k < 4; k++) acc[i][j][k] = 0.f;

    uint4 ahv[2], alv[2];
    float4 bv[2];
    const int NS = FF / 32;  // 176

    ahv[0] = *(const uint4*)(apHh + 0);
    ahv[1] = *(const uint4*)(apHh + 8);
    alv[0] = *(const uint4*)(apHl + 0);
    alv[1] = *(const uint4*)(apHl + 8);
    bv[0]  = *(const float4*)(apB + 0);
    bv[1]  = *(const float4*)(apB + 4);
    {
        char* st = sm;
        *(uint4*)(st + S2_AH + tile_off(arow, acb))     = ahv[0];
        *(uint4*)(st + S2_AH + tile_off(arow, acb + 1)) = ahv[1];
        *(uint4*)(st + S2_AL + tile_off(arow, acb))     = alv[0];
        *(uint4*)(st + S2_AL + tile_off(arow, acb + 1)) = alv[1];
        store_split8(st + S2_BH + tile_off(brow, bch), st + S2_BL + tile_off(brow, bch), bv[0], bv[1]);
    }
    __syncthreads();

#pragma unroll 1
    for (int s = 0; s < NS; s++) {
        if (s + 1 < NS) {
            const __nv_bfloat16* ph = apHh + (s + 1) * 32;
            const __nv_bfloat16* pl = apHl + (s + 1) * 32;
            ahv[0] = *(const uint4*)(ph + 0);
            ahv[1] = *(const uint4*)(ph + 8);
            alv[0] = *(const uint4*)(pl + 0);
            alv[1] = *(const uint4*)(pl + 8);
            const float* pb = apB + (s + 1) * 32;
            bv[0] = *(const float4*)(pb + 0);
            bv[1] = *(const float4*)(pb + 4);
        }
        uint32_t sb = sbu + (uint32_t)(s & 1) * STAGE2;
#pragma unroll
        for (int kk = 0; kk < 2; kk++) {
            int c0 = kk * 2;
            uint32_t ah[2][4], al[2][4];
#pragma unroll
            for (int mt = 0; mt < 2; mt++) {
                int row = wm * 32 + mt * 16 + laneA_row;
                int ch  = c0 + laneA_c;
                uint32_t ad = sb + S2_AH + tile_off(row, ch);
                LDSM_X4(ah[mt][0], ah[mt][1], ah[mt][2], ah[mt][3], ad);
                LDSM_X4(al[mt][0], al[mt][1], al[mt][2], al[mt][3], ad + (S2_AL - S2_AH));
            }
            uint32_t bh[2][4], bl[2][4];
#pragma unroll
            for (int g2 = 0; g2 < 2; g2++) {
                int row = wn * 32 + g2 * 16 + laneB_row;
                int ch  = c0 + laneB_c;
                uint32_t bd = sb + S2_BH + tile_off(row, ch);
                LDSM_X4(bh[g2][0], bh[g2][1], bh[g2][2], bh[g2][3], bd);
                LDSM_X4(bl[g2][0], bl[g2][1], bl[g2][2], bl[g2][3], bd + (S2_BL - S2_BH));
            }
#pragma unroll
            for (int mt = 0; mt < 2; mt++)
#pragma unroll
                for (int nt = 0; nt < 4; nt++) {
                    int gi = nt >> 1, pi = (nt & 1) * 2;
                    MMA16816(acc[mt][nt], ah[mt], bh[gi][pi], bh[gi][pi + 1]);
                    MMA16816(acc[mt][nt], ah[mt], bl[gi][pi], bl[gi][pi + 1]);
                    MMA16816(acc[mt][nt], al[mt], bh[gi][pi], bh[gi][pi + 1]);
                }
        }
        __syncthreads();
        if (s + 1 < NS) {
            char* st = sm + ((s + 1) & 1) * STAGE2;
            *(uint4*)(st + S2_AH + tile_off(arow, acb))     = ahv[0];
            *(uint4*)(st + S2_AH + tile_off(arow, acb + 1)) = ahv[1];
            *(uint4*)(st + S2_AL + tile_off(arow, acb))     = alv[0];
            *(uint4*)(st + S2_AL + tile_off(arow, acb + 1)) = alv[1];
            store_split8(st + S2_BH + tile_off(brow, bch), st + S2_BL + tile_off(brow, bch), bv[0], bv[1]);
            __syncthreads();
        }
    }

    // epilogue: weighted scatter-add (exactly 2 adds/element -> deterministic-ish, fp32)
#pragma unroll
    for (int mt = 0; mt < 2; mt++) {
#pragma unroll
        for (int half = 0; half < 2; half++) {
            int lrow = wm * 32 + mt * 16 + (lane >> 2) + half * 8;
            int rr = m0 + lrow;
            if (rr < cnt) {
                int tok = s_tok[lrow];
                float w = s_w[lrow];
                float* orow = out + (size_t)tok * DIM + n0 + wn * 32 + (lane & 3) * 2;
#pragma unroll
                for (int nt = 0; nt < 4; nt++) {
                    atomicAdd(orow + nt * 8 + 0, w * acc[mt][nt][half * 2 + 0]);
                    atomicAdd(orow + nt * 8 + 1, w * acc[mt][nt][half * 2 + 1]);
                }
            }
        }
    }
}

// ===================== launcher =============================================
extern "C" void kernel_launch(void* const* d_in, const int* in_sizes, int n_in,
                              void* d_out, int out_size) {
    const float* x  = (const float*)d_in[0];
    const float* rw = (const float*)d_in[1];
    const float* gw = (const float*)d_in[2];
    const float* uw = (const float*)d_in[3];
    const float* dw = (const float*)d_in[4];
    float* out = (float*)d_out;

    cudaFuncSetAttribute(gemm1_mma, cudaFuncAttributeMaxDynamicSharedMemorySize, G1_SMEM);
    cudaFuncSetAttribute(gemm2_mma, cudaFuncAttributeMaxDynamicSharedMemorySize, G2_SMEM);

    cudaMemsetAsync(out, 0, (size_t)N_TOK * DIM * sizeof(float));
    zero_small_kernel<<<1, 32>>>();
    router_kernel<<<N_TOK / 8, 256>>>(x, rw);
    finalize_kernel<<<1, 1>>>(out, (long long)out_size);
    scatter_kernel<<<N_TOK / 256, 256>>>();
    gemm1_mma<<<dim3(FF / 64, 2 * N_TOK / 128, NE), 256, G1_SMEM>>>(x, gw, uw);
    gemm2_mma<<<dim3(DIM / 64, 2 * N_TOK / 128, NE), 256, G2_SMEM>>>(dw, out);
}

// round 4
// speedup vs baseline: 3.1269x; 1.1652x over previous
#include <cuda_runtime.h>
#include <cuda_bf16.h>
#include <cstdint>
#include <math.h>

#define N_TOK 8192
#define DIM   2048
#define FF    5632
#define NE    8

// ===================== helpers =============================================
__device__ __forceinline__ uint32_t smem_to_u32(const void* p) {
    uint32_t a;
    asm("{ .reg .u64 t; cvta.to.shared.u64 t, %1; cvt.u32.u64 %0, t; }"
        : "=r"(a) : "l"(p));
    return a;
}

#define LDSM_X4(r0, r1, r2, r3, addr) \
    asm volatile("ldmatrix.sync.aligned.m8n8.x4.shared.b16 {%0,%1,%2,%3}, [%4];" \
                 : "=r"(r0), "=r"(r1), "=r"(r2), "=r"(r3) : "r"(addr))

#define MMA16816(c, a, b0, b1) \
    asm volatile("mma.sync.aligned.m16n8k16.row.col.f32.bf16.bf16.f32 " \
                 "{%0,%1,%2,%3},{%4,%5,%6,%7},{%8,%9},{%0,%1,%2,%3};" \
                 : "+f"((c)[0]), "+f"((c)[1]), "+f"((c)[2]), "+f"((c)[3]) \
                 : "r"((a)[0]), "r"((a)[1]), "r"((a)[2]), "r"((a)[3]), \
                   "r"(b0), "r"(b1))

#define CP_ASYNC16(saddr, gptr) \
    asm volatile("cp.async.cg.shared.global [%0], [%1], 16;" \
                 :: "r"(saddr), "l"(gptr) : "memory")
#define CP_COMMIT() asm volatile("cp.async.commit_group;" ::: "memory")
#define CP_WAIT2()  asm volatile("cp.async.wait_group 2;" ::: "memory")

// fp32 -> (hi,lo) bf16 split, 2 values packed per uint32
__device__ __forceinline__ void split2(float a, float b, uint32_t& hi, uint32_t& lo) {
    __nv_bfloat16 ha = __float2bfloat16_rn(a);
    __nv_bfloat16 hb = __float2bfloat16_rn(b);
    float ra = a - __bfloat162float(ha);
    float rb = b - __bfloat162float(hb);
    __nv_bfloat162 h; h.x = ha; h.y = hb;
    __nv_bfloat162 l; l.x = __float2bfloat16_rn(ra); l.y = __float2bfloat16_rn(rb);
    hi = *reinterpret_cast<uint32_t*>(&h);
    lo = *reinterpret_cast<uint32_t*>(&l);
}

// byte offset within a [rows][32 bf16] tile, 64B rows, xor swizzle for ldmatrix
__device__ __forceinline__ uint32_t tile_off(int row, int chunk) {
    return (uint32_t)(row * 64 + ((chunk ^ ((row >> 1) & 3)) << 4));
}

// ===================== scratch =============================================
__device__ int   g_cnt[NE];
__device__ float g_psum[NE];
__device__ int   g_off[NE];
__device__ int   g_cursor[NE];
__device__ int   g_top_id[N_TOK * 2];
__device__ float g_top_w[N_TOK * 2];
__device__ int   g_row_tok[N_TOK * 2];
__device__ float g_row_w[N_TOK * 2];
__device__ __align__(16) __nv_bfloat16 g_Hhi[(size_t)N_TOK * 2 * FF];
__device__ __align__(16) __nv_bfloat16 g_Hlo[(size_t)N_TOK * 2 * FF];
// pre-split operands
__device__ __align__(16) __nv_bfloat16 g_xhi[(size_t)N_TOK * DIM];
__device__ __align__(16) __nv_bfloat16 g_xlo[(size_t)N_TOK * DIM];
__device__ __align__(16) __nv_bfloat16 g_gwhi[(size_t)NE * FF * DIM];
__device__ __align__(16) __nv_bfloat16 g_gwlo[(size_t)NE * FF * DIM];
__device__ __align__(16) __nv_bfloat16 g_uwhi[(size_t)NE * FF * DIM];
__device__ __align__(16) __nv_bfloat16 g_uwlo[(size_t)NE * FF * DIM];
__device__ __align__(16) __nv_bfloat16 g_dwhi[(size_t)NE * DIM * FF];
__device__ __align__(16) __nv_bfloat16 g_dwlo[(size_t)NE * DIM * FF];

// ===================== pre-split kernel =====================================
__global__ __launch_bounds__(256)
void split_kernel(const float* __restrict__ src,
                  __nv_bfloat16* __restrict__ hi,
                  __nv_bfloat16* __restrict__ lo, size_t n) {
    size_t i = ((size_t)blockIdx.x * blockDim.x + threadIdx.x) * 8;
    if (i >= n) return;
    float4 a = *(const float4*)(src + i);
    float4 b = *(const float4*)(src + i + 4);
    uint32_t h0, l0, h1, l1, h2, l2, h3, l3;
    split2(a.x, a.y, h0, l0);
    split2(a.z, a.w, h1, l1);
    split2(b.x, b.y, h2, l2);
    split2(b.z, b.w, h3, l3);
    *(uint4*)(hi + i) = make_uint4(h0, h1, h2, h3);
    *(uint4*)(lo + i) = make_uint4(l0, l1, l2, l3);
}

// ===================== router pipeline ======================================
__global__ void zero_small_kernel() {
    int i = threadIdx.x;
    if (i < NE) { g_cnt[i] = 0; g_psum[i] = 0.f; }
}

__global__ void router_kernel(const float* __restrict__ x,
                              const float* __restrict__ rw) {
    int warp = threadIdx.x >> 5;
    int lane = threadIdx.x & 31;
    int t = blockIdx.x * 8 + warp;
    if (t >= N_TOK) return;
    const float* xr = x + (size_t)t * DIM;
    float acc[NE];
#pragma unroll
    for (int e = 0; e < NE; e++) acc[e] = 0.f;
    for (int d = lane; d < DIM; d += 32) {
        float xv = xr[d];
#pragma unroll
        for (int e = 0; e < NE; e++) acc[e] += xv * rw[e * DIM + d];
    }
#pragma unroll
    for (int off = 16; off > 0; off >>= 1) {
#pragma unroll
        for (int e = 0; e < NE; e++)
            acc[e] += __shfl_xor_sync(0xffffffffu, acc[e], off);
    }
    float mx = acc[0];
#pragma unroll
    for (int e = 1; e < NE; e++) mx = fmaxf(mx, acc[e]);
    float p[NE], s = 0.f;
#pragma unroll
    for (int e = 0; e < NE; e++) { p[e] = expf(acc[e] - mx); s += p[e]; }
    float inv = 1.f / s;
#pragma unroll
    for (int e = 0; e < NE; e++) p[e] *= inv;
    float m1 = -1.f, m2 = -1.f; int i1 = 0, i2 = 0;
#pragma unroll
    for (int e = 0; e < NE; e++) {
        if (p[e] > m1) { m2 = m1; i2 = i1; m1 = p[e]; i1 = e; }
        else if (p[e] > m2) { m2 = p[e]; i2 = e; }
    }
    if (lane == 0) {
        atomicAdd(&g_cnt[i1], 1);
        atomicAdd(&g_cnt[i2], 1);
#pragma unroll
        for (int e = 0; e < NE; e++) atomicAdd(&g_psum[e], p[e]);
        float sw = 1.f / (m1 + m2);
        g_top_id[2 * t + 0] = i1;  g_top_w[2 * t + 0] = m1 * sw;
        g_top_id[2 * t + 1] = i2;  g_top_w[2 * t + 1] = m2 * sw;
    }
}

__global__ void finalize_kernel(float* __restrict__ out, long long out_size) {
    if (threadIdx.x != 0 || blockIdx.x != 0) return;
    int o = 0;
    for (int e = 0; e < NE; e++) { g_off[e] = o; g_cursor[e] = o; o += g_cnt[e]; }
    float aux = 0.f;
    for (int e = 0; e < NE; e++) aux += g_psum[e] * (float)g_cnt[e];
    aux *= (float)NE / ((float)N_TOK * (float)N_TOK);
    if (out_size > (long long)N_TOK * DIM)
        out[(size_t)N_TOK * DIM] = aux;
}

__global__ void scatter_kernel() {
    int t = blockIdx.x * blockDim.x + threadIdx.x;
    if (t >= N_TOK) return;
#pragma unroll
    for (int s = 0; s < 2; s++) {
        int e = g_top_id[2 * t + s];
        int pos = atomicAdd(&g_cursor[e], 1);
        g_row_tok[pos] = t;
        g_row_w[pos] = g_top_w[2 * t + s];
    }
}

// ===================== GEMM1: H = silu(X Gw^T) * (X Uw^T) ===================
// cp.async 4-stage pipeline, pre-split bf16 operands. CTA 128x64, BK=32.
#define S1_AH 0
#define S1_AL 8192
#define S1_GH 16384
#define S1_GL 20480
#define S1_UH 24576
#define S1_UL 28672
#define STAGE1 32768
#define G1_SMEM (4 * STAGE1)

__global__ __launch_bounds__(256)
void gemm1_mma(const float* __restrict__ x_unused) {
    int e   = blockIdx.z;
    int cnt = g_cnt[e];
    int m0  = blockIdx.y * 128;
    if (m0 >= cnt) return;
    int n0  = blockIdx.x * 64;
    int off = g_off[e];

    extern __shared__ char sm[];
    __shared__ int s_tok[128];
    int tid = threadIdx.x;
    if (tid < 128) {
        int rr = m0 + tid;
        s_tok[tid] = (rr < cnt) ? g_row_tok[off + rr] : g_row_tok[off];
    }
    __syncthreads();
    uint32_t sbu = smem_to_u32(sm);

    // ---- fill mapping: per-thread 8 cp.asyncs/stage
    int rowA0 = tid >> 2;
    int rowA1 = 64 + (tid >> 2);
    int seg   = tid & 3;                 // 16B unit within 64B row
    uint32_t offA0 = tile_off(rowA0, seg);
    uint32_t offA1 = tile_off(rowA1, seg);
    uint32_t offB  = offA0;              // B tiles have 64 rows, same mapping as rowA0
    const __nv_bfloat16* gA0h = g_xhi + (size_t)s_tok[rowA0] * DIM + seg * 8;
    const __nv_bfloat16* gA0l = g_xlo + (size_t)s_tok[rowA0] * DIM + seg * 8;
    const __nv_bfloat16* gA1h = g_xhi + (size_t)s_tok[rowA1] * DIM + seg * 8;
    const __nv_bfloat16* gA1l = g_xlo + (size_t)s_tok[rowA1] * DIM + seg * 8;
    size_t brow = (size_t)e * FF + n0 + rowA0;
    const __nv_bfloat16* gGh = g_gwhi + brow * DIM + seg * 8;
    const __nv_bfloat16* gGl = g_gwlo + brow * DIM + seg * 8;
    const __nv_bfloat16* gUh = g_uwhi + brow * DIM + seg * 8;
    const __nv_bfloat16* gUl = g_uwlo + brow * DIM + seg * 8;

    // ---- frag mapping
    int lane = tid & 31, warp = tid >> 5;
    int wm = warp & 3, wn = warp >> 2;
    int laneA_row = lane & 15;
    int laneA_c   = lane >> 4;
    int laneB_row = (lane & 7) | ((lane >> 1) & 8);
    int laneB_c   = (lane >> 3) & 1;

    float gacc[2][4][4], uacc[2][4][4];
#pragma unroll
    for (int i = 0; i < 2; i++)
#pragma unroll
        for (int j = 0; j < 4; j++)
#pragma unroll
            for (int k = 0; k < 4; k++) { gacc[i][j][k] = 0.f; uacc[i][j][k] = 0.f; }

    const int NS = DIM / 32;  // 64

#define G1_FILL(s_) do { \
    uint32_t sb_ = sbu + (uint32_t)((s_) & 3) * STAGE1; \
    int k0_ = (s_) * 32; \
    CP_ASYNC16(sb_ + S1_AH + offA0, gA0h + k0_); \
    CP_ASYNC16(sb_ + S1_AH + offA1, gA1h + k0_); \
    CP_ASYNC16(sb_ + S1_AL + offA0, gA0l + k0_); \
    CP_ASYNC16(sb_ + S1_AL + offA1, gA1l + k0_); \
    CP_ASYNC16(sb_ + S1_GH + offB,  gGh + k0_); \
    CP_ASYNC16(sb_ + S1_GL + offB,  gGl + k0_); \
    CP_ASYNC16(sb_ + S1_UH + offB,  gUh + k0_); \
    CP_ASYNC16(sb_ + S1_UL + offB,  gUl + k0_); \
    CP_COMMIT(); \
} while (0)

    G1_FILL(0); G1_FILL(1); G1_FILL(2);

#pragma unroll 1
    for (int s = 0; s < NS; s++) {
        CP_WAIT2();
        __syncthreads();
        if (s + 3 < NS) G1_FILL(s + 3);
        uint32_t sb = sbu + (uint32_t)(s & 3) * STAGE1;
#pragma unroll
        for (int kk = 0; kk < 2; kk++) {
            int c0 = kk * 2;
            uint32_t ah[2][4], al[2][4];
#pragma unroll
            for (int mt = 0; mt < 2; mt++) {
                int row = wm * 32 + mt * 16 + laneA_row;
                int ch  = c0 + laneA_c;
                uint32_t ad = sb + S1_AH + tile_off(row, ch);
                LDSM_X4(ah[mt][0], ah[mt][1], ah[mt][2], ah[mt][3], ad);
                LDSM_X4(al[mt][0], al[mt][1], al[mt][2], al[mt][3], ad + (S1_AL - S1_AH));
            }
            {   // gate
                uint32_t bh[2][4], bl[2][4];
#pragma unroll
                for (int g2 = 0; g2 < 2; g2++) {
                    int row = wn * 32 + g2 * 16 + laneB_row;
                    int ch  = c0 + laneB_c;
                    uint32_t bd = sb + S1_GH + tile_off(row, ch);
                    LDSM_X4(bh[g2][0], bh[g2][1], bh[g2][2], bh[g2][3], bd);
                    LDSM_X4(bl[g2][0], bl[g2][1], bl[g2][2], bl[g2][3], bd + (S1_GL - S1_GH));
                }
#pragma unroll
                for (int mt = 0; mt < 2; mt++)
#pragma unroll
                    for (int nt = 0; nt < 4; nt++) {
                        int gi = nt >> 1, pi = (nt & 1) * 2;
                        MMA16816(gacc[mt][nt], ah[mt], bh[gi][pi], bh[gi][pi + 1]);
                        MMA16816(gacc[mt][nt], ah[mt], bl[gi][pi], bl[gi][pi + 1]);
                        MMA16816(gacc[mt][nt], al[mt], bh[gi][pi], bh[gi][pi + 1]);
                    }
            }
            {   // up
                uint32_t bh[2][4], bl[2][4];
#pragma unroll
                for (int g2 = 0; g2 < 2; g2++) {
                    int row = wn * 32 + g2 * 16 + laneB_row;
                    int ch  = c0 + laneB_c;
                    uint32_t bd = sb + S1_UH + tile_off(row, ch);
                    LDSM_X4(bh[g2][0], bh[g2][1], bh[g2][2], bh[g2][3], bd);
                    LDSM_X4(bl[g2][0], bl[g2][1], bl[g2][2], bl[g2][3], bd + (S1_UL - S1_UH));
                }
#pragma unroll
                for (int mt = 0; mt < 2; mt++)
#pragma unroll
                    for (int nt = 0; nt < 4; nt++) {
                        int gi = nt >> 1, pi = (nt & 1) * 2;
                        MMA16816(uacc[mt][nt], ah[mt], bh[gi][pi], bh[gi][pi + 1]);
                        MMA16816(uacc[mt][nt], ah[mt], bl[gi][pi], bl[gi][pi + 1]);
                        MMA16816(uacc[mt][nt], al[mt], bh[gi][pi], bh[gi][pi + 1]);
                    }
            }
        }
        __syncthreads();
    }

    // epilogue: h = silu(g)*u -> split bf16 hi/lo -> g_H
#pragma unroll
    for (int mt = 0; mt < 2; mt++) {
#pragma unroll
        for (int half = 0; half < 2; half++) {
            int rr = m0 + wm * 32 + mt * 16 + (lane >> 2) + half * 8;
            if (rr < cnt) {
                size_t rb = (size_t)(off + rr) * FF + n0 + wn * 32 + (lane & 3) * 2;
#pragma unroll
                for (int nt = 0; nt < 4; nt++) {
                    float g0 = gacc[mt][nt][half * 2 + 0];
                    float g1 = gacc[mt][nt][half * 2 + 1];
                    float u0 = uacc[mt][nt][half * 2 + 0];
                    float u1 = uacc[mt][nt][half * 2 + 1];
                    float h0 = g0 / (1.f + __expf(-g0)) * u0;
                    float h1 = g1 / (1.f + __expf(-g1)) * u1;
                    uint32_t hh, hl;
                    split2(h0, h1, hh, hl);
                    *(uint32_t*)(g_Hhi + rb + nt * 8) = hh;
                    *(uint32_t*)(g_Hlo + rb + nt * 8) = hl;
                }
            }
        }
    }
}

// ===================== GEMM2: out += w * (H Dw^T) ===========================
#define S2_AH 0
#define S2_AL 8192
#define S2_BH 16384
#define S2_BL 20480
#define STAGE2 24576
#define G2_SMEM (4 * STAGE2)

__global__ __launch_bounds__(256)
void gemm2_mma(float* __restrict__ out) {
    int e   = blockIdx.z;
    int cnt = g_cnt[e];
    int m0  = blockIdx.y * 128;
    if (m0 >= cnt) return;
    int n0  = blockIdx.x * 64;
    int off = g_off[e];

    extern __shared__ char sm[];
    __shared__ int   s_tok[128];
    __shared__ float s_w[128];
    int tid = threadIdx.x;
    if (tid < 128) {
        int rr = m0 + tid;
        bool v = rr < cnt;
        s_tok[tid] = v ? g_row_tok[off + rr] : 0;
        s_w[tid]   = v ? g_row_w[off + rr] : 0.f;
    }
    __syncthreads();
    uint32_t sbu = smem_to_u32(sm);

    int rowA0 = tid >> 2;
    int rowA1 = 64 + (tid >> 2);
    int seg   = tid & 3;
    uint32_t offA0 = tile_off(rowA0, seg);
    uint32_t offA1 = tile_off(rowA1, seg);
    uint32_t offB  = offA0;
    int hr0 = (m0 + rowA0 < cnt) ? (off + m0 + rowA0) : off;
    int hr1 = (m0 + rowA1 < cnt) ? (off + m0 + rowA1) : off;
    const __nv_bfloat16* gA0h = g_Hhi + (size_t)hr0 * FF + seg * 8;
    const __nv_bfloat16* gA0l = g_Hlo + (size_t)hr0 * FF + seg * 8;
    const __nv_bfloat16* gA1h = g_Hhi + (size_t)hr1 * FF + seg * 8;
    const __nv_bfloat16* gA1l = g_Hlo + (size_t)hr1 * FF + seg * 8;
    size_t brow = (size_t)e * DIM + n0 + rowA0;
    const __nv_bfloat16* gBh = g_dwhi + brow * FF + seg * 8;
    const __nv_bfloat16* gBl = g_dwlo + brow * FF + seg * 8;

    int lane = tid & 31, warp = tid >> 5;
    int wm = warp & 3, wn = warp >> 2;
    int laneA_row = lane & 15;
    int laneA_c   = lane >> 4;
    int laneB_row = (lane & 7) | ((lane >> 1) & 8);
    int laneB_c   = (lane >> 3) & 1;

    float acc[2][4][4];
#pragma unroll
    for (int i = 0; i < 2; i++)
#pragma unroll
        for (int j = 0; j < 4; j++)
#pragma unroll
            for (int k = 0; k < 4; k++) acc[i][j][k] = 0.f;

    const int NS = FF / 32;  // 176

#define G2_FILL(s_) do { \
    uint32_t sb_ = sbu + (uint32_t)((s_) & 3) * STAGE2; \
    int k0_ = (s_) * 32; \
    CP_ASYNC16(sb_ + S2_AH + offA0, gA0h + k0_); \
    CP_ASYNC16(sb_ + S2_AH + offA1, gA1h + k0_); \
    CP_ASYNC16(sb_ + S2_AL + offA0, gA0l + k0_); \
    CP_ASYNC16(sb_ + S2_AL + offA1, gA1l + k0_); \
    CP_ASYNC16(sb_ + S2_BH + offB,  gBh + k0_); \
    CP_ASYNC16(sb_ + S2_BL + offB,  gBl + k0_); \
    CP_COMMIT(); \
} while (0)

    G2_FILL(0); G2_FILL(1); G2_FILL(2);

#pragma unroll 1
    for (int s = 0; s < NS; s++) {
        CP_WAIT2();
        __syncthreads();
        if (s + 3 < NS) G2_FILL(s + 3);
        uint32_t sb = sbu + (uint32_t)(s & 3) * STAGE2;
#pragma unroll
        for (int kk = 0; kk < 2; kk++) {
            int c0 = kk * 2;
            uint32_t ah[2][4], al[2][4];
#pragma unroll
            for (int mt = 0; mt < 2; mt++) {
                int row = wm * 32 + mt * 16 + laneA_row;
                int ch  = c0 + laneA_c;
                uint32_t ad = sb + S2_AH + tile_off(row, ch);
                LDSM_X4(ah[mt][0], ah[mt][1], ah[mt][2], ah[mt][3], ad);
                LDSM_X4(al[mt][0], al[mt][1], al[mt][2], al[mt][3], ad + (S2_AL - S2_AH));
            }
            uint32_t bh[2][4], bl[2][4];
#pragma unroll
            for (int g2 = 0; g2 < 2; g2++) {
                int row = wn * 32 + g2 * 16 + laneB_row;
                int ch  = c0 + laneB_c;
                uint32_t bd = sb + S2_BH + tile_off(row, ch);
                LDSM_X4(bh[g2][0], bh[g2][1], bh[g2][2], bh[g2][3], bd);
                LDSM_X4(bl[g2][0], bl[g2][1], bl[g2][2], bl[g2][3], bd + (S2_BL - S2_BH));
            }
#pragma unroll
            for (int mt = 0; mt < 2; mt++)
#pragma unroll
                for (int nt = 0; nt < 4; nt++) {
                    int gi = nt >> 1, pi = (nt & 1) * 2;
                    MMA16816(acc[mt][nt], ah[mt], bh[gi][pi], bh[gi][pi + 1]);
                    MMA16816(acc[mt][nt], ah[mt], bl[gi][pi], bl[gi][pi + 1]);
                    MMA16816(acc[mt][nt], al[mt], bh[gi][pi], bh[gi][pi + 1]);
                }
        }
        __syncthreads();
    }

    // epilogue: weighted scatter-add (exactly 2 adds/element)
#pragma unroll
    for (int mt = 0; mt < 2; mt++) {
#pragma unroll
        for (int half = 0; half < 2; half++) {
            int lrow = wm * 32 + mt * 16 + (lane >> 2) + half * 8;
            int rr = m0 + lrow;
            if (rr < cnt) {
                int tok = s_tok[lrow];
                float w = s_w[lrow];
                float* orow = out + (size_t)tok * DIM + n0 + wn * 32 + (lane & 3) * 2;
#pragma unroll
                for (int nt = 0; nt < 4; nt++) {
                    atomicAdd(orow + nt * 8 + 0, w * acc[mt][nt][half * 2 + 0]);
                    atomicAdd(orow + nt * 8 + 1, w * acc[mt][nt][half * 2 + 1]);
                }
            }
        }
    }
}

// ===================== launcher =============================================
extern "C" void kernel_launch(void* const* d_in, const int* in_sizes, int n_in,
                              void* d_out, int out_size) {
    const float* x  = (const float*)d_in[0];
    const float* rw = (const float*)d_in[1];
    const float* gw = (const float*)d_in[2];
    const float* uw = (const float*)d_in[3];
    const float* dw = (const float*)d_in[4];
    float* out = (float*)d_out;

    cudaFuncSetAttribute(gemm1_mma, cudaFuncAttributeMaxDynamicSharedMemorySize, G1_SMEM);
    cudaFuncSetAttribute(gemm2_mma, cudaFuncAttributeMaxDynamicSharedMemorySize, G2_SMEM);

    cudaMemsetAsync(out, 0, (size_t)N_TOK * DIM * sizeof(float));
    zero_small_kernel<<<1, 32>>>();

    // pre-split operands into bf16 hi/lo
    {
        size_t nx = (size_t)N_TOK * DIM;          // 16.8M
        size_t nw = (size_t)NE * FF * DIM;        // 92.3M
        __nv_bfloat16 *xh, *xl, *gh, *gl, *uh, *ul, *dh, *dl;
        cudaGetSymbolAddress((void**)&xh, g_xhi);
        cudaGetSymbolAddress((void**)&xl, g_xlo);
        cudaGetSymbolAddress((void**)&gh, g_gwhi);
        cudaGetSymbolAddress((void**)&gl, g_gwlo);
        cudaGetSymbolAddress((void**)&uh, g_uwhi);
        cudaGetSymbolAddress((void**)&ul, g_uwlo);
        cudaGetSymbolAddress((void**)&dh, g_dwhi);
        cudaGetSymbolAddress((void**)&dl, g_dwlo);
        split_kernel<<<(unsigned)(nx / 2048), 256>>>(x, xh, xl, nx);
        split_kernel<<<(unsigned)(nw / 2048), 256>>>(gw, gh, gl, nw);
        split_kernel<<<(unsigned)(nw / 2048), 256>>>(uw, uh, ul, nw);
        split_kernel<<<(unsigned)(nw / 2048), 256>>>(dw, dh, dl, nw);
    }

    router_kernel<<<N_TOK / 8, 256>>>(x, rw);
    finalize_kernel<<<1, 1>>>(out, (long long)out_size);
    scatter_kernel<<<N_TOK / 256, 256>>>();
    gemm1_mma<<<dim3(FF / 64, 2 * N_TOK / 128, NE), 256, G1_SMEM>>>(x);
    gemm2_mma<<<dim3(DIM / 64, 2 * N_TOK / 128, NE), 256, G2_SMEM>>>(out);
}